// round 1
// baseline (speedup 1.0000x reference)
#include <cuda_runtime.h>

#define NROWS 8192
#define HID   1024
#define PROJ  128
#define NSPLIT 4          // column splits for the fused sims/lse kernel

// ---- scratch (device globals; no runtime allocation allowed) ----
__device__ float g_h[NROWS * HID];        // h, then layernormed in place
__device__ float g_z[NROWS * PROJ];       // projection output
__device__ float g_m[NSPLIT * NROWS];     // per-split running max (base-2 logits)
__device__ float g_s[NSPLIT * NROWS];     // per-split running sumexp2
__device__ float g_pos[NROWS];            // raw positive sim  z_i . z_{p(i)}

// log2(e)/T  and  ln(2), 1/T
#define C2F  20.6099291555566200f
#define LN2F 0.6931471805599453f
#define INVT 14.2857142857142857f

// =====================================================================
// Kernel 1: h = gelu(x @ W + b)     [8192x1024] = [8192x1024]@[1024x1024]
// 128x128 tile, BK=8, 256 threads, 8x8 microtile, reg-prefetch of gmem.
// =====================================================================
__global__ __launch_bounds__(256) void k_gemm1(const float* __restrict__ x,
                                               const float* __restrict__ w,
                                               const float* __restrict__ bias) {
    __shared__ float As[8][128];   // [k][row]
    __shared__ float Bs[8][128];   // [k][col]
    const int tid  = threadIdx.x;
    const int row0 = blockIdx.y * 128;
    const int col0 = blockIdx.x * 128;
    const int tx = tid & 15, ty = tid >> 4;
    const int arow = tid >> 1, ak = (tid & 1) * 4;
    const int bk = tid >> 5,  bc = (tid & 31) * 4;

    const float* xp = x + (row0 + arow) * HID + ak;
    const float* wp = w + bk * HID + col0 + bc;

    float acc[8][8];
#pragma unroll
    for (int i = 0; i < 8; i++)
#pragma unroll
        for (int j = 0; j < 8; j++) acc[i][j] = 0.f;

    float4 av = *(const float4*)(xp);
    float4 bv = *(const float4*)(wp);

    for (int k0 = 0; k0 < HID; k0 += 8) {
        __syncthreads();
        As[ak+0][arow] = av.x; As[ak+1][arow] = av.y;
        As[ak+2][arow] = av.z; As[ak+3][arow] = av.w;
        *(float4*)&Bs[bk][bc] = bv;
        __syncthreads();
        if (k0 + 8 < HID) {
            av = *(const float4*)(xp + (k0 + 8));
            bv = *(const float4*)(wp + (size_t)(k0 + 8) * HID);
        }
#pragma unroll
        for (int k = 0; k < 8; k++) {
            float a[8], b[8];
            *(float4*)&a[0] = *(const float4*)&As[k][ty*8];
            *(float4*)&a[4] = *(const float4*)&As[k][ty*8+4];
            *(float4*)&b[0] = *(const float4*)&Bs[k][tx*8];
            *(float4*)&b[4] = *(const float4*)&Bs[k][tx*8+4];
#pragma unroll
            for (int i = 0; i < 8; i++)
#pragma unroll
                for (int j = 0; j < 8; j++)
                    acc[i][j] = fmaf(a[i], b[j], acc[i][j]);
        }
    }
#pragma unroll
    for (int i = 0; i < 8; i++) {
        const int r = row0 + ty*8 + i;
#pragma unroll
        for (int j = 0; j < 8; j++) {
            const int c = col0 + tx*8 + j;
            const float h = acc[i][j] + bias[c];
            // exact (erf) GELU, as in the reference
            g_h[(size_t)r * HID + c] = 0.5f * h * (1.0f + erff(h * 0.70710678118654752f));
        }
    }
}

// =====================================================================
// Kernel 2: row LayerNorm, in place on g_h.  One block per row.
// =====================================================================
__global__ __launch_bounds__(256) void k_ln(const float* __restrict__ gamma,
                                            const float* __restrict__ beta) {
    const int row = blockIdx.x;
    const int tid = threadIdx.x;
    float* hr = g_h + (size_t)row * HID;
    float4 v = *(float4*)(hr + tid * 4);

    __shared__ float red[8];
    __shared__ float bcast;

    float s = v.x + v.y + v.z + v.w;
#pragma unroll
    for (int m = 16; m > 0; m >>= 1) s += __shfl_xor_sync(0xffffffffu, s, m);
    if ((tid & 31) == 0) red[tid >> 5] = s;
    __syncthreads();
    if (tid == 0) {
        float t = 0.f;
#pragma unroll
        for (int i = 0; i < 8; i++) t += red[i];
        bcast = t * (1.0f / HID);
    }
    __syncthreads();
    const float mu = bcast;

    const float dx = v.x - mu, dy = v.y - mu, dz = v.z - mu, dw = v.w - mu;
    float q = dx*dx + dy*dy + dz*dz + dw*dw;
#pragma unroll
    for (int m = 16; m > 0; m >>= 1) q += __shfl_xor_sync(0xffffffffu, q, m);
    __syncthreads();
    if ((tid & 31) == 0) red[tid >> 5] = q;
    __syncthreads();
    if (tid == 0) {
        float t = 0.f;
#pragma unroll
        for (int i = 0; i < 8; i++) t += red[i];
        bcast = rsqrtf(t * (1.0f / HID) + 1e-12f);
    }
    __syncthreads();
    const float inv = bcast;

    const float4 g  = *(const float4*)(gamma + tid * 4);
    const float4 be = *(const float4*)(beta  + tid * 4);
    v.x = dx * inv * g.x + be.x;
    v.y = dy * inv * g.y + be.y;
    v.z = dz * inv * g.z + be.z;
    v.w = dw * inv * g.w + be.w;
    *(float4*)(hr + tid * 4) = v;
}

// =====================================================================
// Kernel 3: z = hn @ dec_w + dec_b   [8192x128] = [8192x1024]@[1024x128]
// 32x128 tile, BK=16, 256 threads, 4x4 microtile.
// =====================================================================
__global__ __launch_bounds__(256) void k_gemm2(const float* __restrict__ w,
                                               const float* __restrict__ bias) {
    __shared__ float As[16][32];    // [k][row]
    __shared__ float Bs[16][128];   // [k][col]
    const int tid  = threadIdx.x;
    const int row0 = blockIdx.x * 32;
    const int tx = tid & 31, ty = tid >> 5;     // cols tx*4, rows ty*4
    const int ar  = tid >> 3, akk = (tid & 7) * 2;
    const int bkk = tid >> 5, bc  = (tid & 31) * 4;

    const float* ap  = g_h + (size_t)(row0 + ar) * HID + akk;
    const float* bp  = w + (size_t)bkk * PROJ + bc;

    float acc[4][4];
#pragma unroll
    for (int i = 0; i < 4; i++)
#pragma unroll
        for (int j = 0; j < 4; j++) acc[i][j] = 0.f;

    float2 a2 = *(const float2*)ap;
    float4 b0 = *(const float4*)bp;
    float4 b1 = *(const float4*)(bp + 8 * PROJ);

    for (int k0 = 0; k0 < HID; k0 += 16) {
        __syncthreads();
        As[akk][ar] = a2.x; As[akk+1][ar] = a2.y;
        *(float4*)&Bs[bkk][bc]     = b0;
        *(float4*)&Bs[bkk+8][bc]   = b1;
        __syncthreads();
        if (k0 + 16 < HID) {
            a2 = *(const float2*)(ap + (k0 + 16));
            b0 = *(const float4*)(bp + (size_t)(k0 + 16) * PROJ);
            b1 = *(const float4*)(bp + (size_t)(k0 + 24) * PROJ);
        }
#pragma unroll
        for (int k = 0; k < 16; k++) {
            float a[4], b[4];
            *(float4*)a = *(const float4*)&As[k][ty*4];
            *(float4*)b = *(const float4*)&Bs[k][tx*4];
#pragma unroll
            for (int i = 0; i < 4; i++)
#pragma unroll
                for (int j = 0; j < 4; j++)
                    acc[i][j] = fmaf(a[i], b[j], acc[i][j]);
        }
    }
#pragma unroll
    for (int i = 0; i < 4; i++) {
        const int r = row0 + ty*4 + i;
#pragma unroll
        for (int j = 0; j < 4; j++) {
            const int c = tx*4 + j;
            g_z[(size_t)r * PROJ + c] = acc[i][j] + bias[c];
        }
    }
}

// =====================================================================
// Kernel 4: fused z@z.T + online logsumexp (base 2), excluding j==i.
// Block = 128 rows x 2048 cols (one of NSPLIT=4 column splits).
// 256 threads, 8x8 microtile over 128x128 col tiles, K = 128 (PROJ).
// Also captures the positive sim z_i . z_{p(i)} into g_pos.
// =====================================================================
__global__ __launch_bounds__(256) void k_sims() {
    extern __shared__ float sm[];
    float* zi = sm;            // [k][row] 128x128
    float* zj = sm + 16384;    // [k][col] 128x128
    const int tid = threadIdx.x;
    const int tx = tid & 15, ty = tid >> 4;
    const int i0 = blockIdx.x * 128;
    const int j0 = blockIdx.y * (NROWS / NSPLIT);

    // load zi, transposed to [k][row]
#pragma unroll
    for (int q = 0; q < 16; q++) {
        const int f  = q * 256 + tid;     // float4 index
        const int r  = f >> 5;
        const int k4 = (f & 31) * 4;
        const float4 v = *(const float4*)&g_z[(size_t)(i0 + r) * PROJ + k4];
        zi[(k4+0)*128 + r] = v.x; zi[(k4+1)*128 + r] = v.y;
        zi[(k4+2)*128 + r] = v.z; zi[(k4+3)*128 + r] = v.w;
    }

    float runm[8], runs[8];
#pragma unroll
    for (int i = 0; i < 8; i++) { runm[i] = -1e30f; runs[i] = 0.f; }

    for (int jt = 0; jt < (NROWS / NSPLIT) / 128; jt++) {
        const int jb = j0 + jt * 128;
        __syncthreads();
#pragma unroll
        for (int q = 0; q < 16; q++) {
            const int f  = q * 256 + tid;
            const int r  = f >> 5;
            const int k4 = (f & 31) * 4;
            const float4 v = *(const float4*)&g_z[(size_t)(jb + r) * PROJ + k4];
            zj[(k4+0)*128 + r] = v.x; zj[(k4+1)*128 + r] = v.y;
            zj[(k4+2)*128 + r] = v.z; zj[(k4+3)*128 + r] = v.w;
        }
        __syncthreads();

        float acc[8][8];
#pragma unroll
        for (int i = 0; i < 8; i++)
#pragma unroll
            for (int j = 0; j < 8; j++) acc[i][j] = 0.f;

#pragma unroll 4
        for (int k = 0; k < 128; k++) {
            float a[8], b[8];
            *(float4*)&a[0] = *(const float4*)&zi[k*128 + ty*8];
            *(float4*)&a[4] = *(const float4*)&zi[k*128 + ty*8 + 4];
            *(float4*)&b[0] = *(const float4*)&zj[k*128 + tx*8];
            *(float4*)&b[4] = *(const float4*)&zj[k*128 + tx*8 + 4];
#pragma unroll
            for (int i = 0; i < 8; i++)
#pragma unroll
                for (int j = 0; j < 8; j++)
                    acc[i][j] = fmaf(a[i], b[j], acc[i][j]);
        }

        // online lse update per row (base-2 domain, u = s * log2(e)/T)
#pragma unroll
        for (int i = 0; i < 8; i++) {
            const int ig = i0 + ty*8 + i;
            const int pg = (ig + 4096) & (NROWS - 1);
            float u[8];
            float tmax = -1e30f;
#pragma unroll
            for (int j = 0; j < 8; j++) {
                const int jg = jb + tx*8 + j;
                const float sv = acc[i][j];
                if (jg == pg) g_pos[ig] = sv;
                const float uu = (jg == ig) ? -3.0e38f : sv * C2F;
                u[j] = uu;
                tmax = fmaxf(tmax, uu);
            }
#pragma unroll
            for (int m = 8; m; m >>= 1)
                tmax = fmaxf(tmax, __shfl_xor_sync(0xffffffffu, tmax, m));
            const float newm = fmaxf(runm[i], tmax);
            float p = 0.f;
#pragma unroll
            for (int j = 0; j < 8; j++) p += exp2f(u[j] - newm);
#pragma unroll
            for (int m = 8; m; m >>= 1) p += __shfl_xor_sync(0xffffffffu, p, m);
            runs[i] = runs[i] * exp2f(runm[i] - newm) + p;
            runm[i] = newm;
        }
    }

    if (tx == 0) {
#pragma unroll
        for (int i = 0; i < 8; i++) {
            const int ig = i0 + ty*8 + i;
            g_m[blockIdx.y * NROWS + ig] = runm[i];
            g_s[blockIdx.y * NROWS + ig] = runs[i];
        }
    }
}

// =====================================================================
// Kernel 5: merge the NSPLIT partial (m, s) pairs per row, compute
// loss_i = ln2*(M + log2(S)) - pos_i / T, reduce mean -> out[0].
// =====================================================================
__global__ __launch_bounds__(1024) void k_final(float* __restrict__ out) {
    const int tid = threadIdx.x;
    float local = 0.f;
    for (int r = tid; r < NROWS; r += 1024) {
        const float m0 = g_m[r];
        const float m1 = g_m[NROWS   + r];
        const float m2 = g_m[2*NROWS + r];
        const float m3 = g_m[3*NROWS + r];
        const float M  = fmaxf(fmaxf(m0, m1), fmaxf(m2, m3));
        const float S  = g_s[r]         * exp2f(m0 - M)
                       + g_s[NROWS+r]   * exp2f(m1 - M)
                       + g_s[2*NROWS+r] * exp2f(m2 - M)
                       + g_s[3*NROWS+r] * exp2f(m3 - M);
        const float lse = (M + log2f(S)) * LN2F;
        local += lse - g_pos[r] * INVT;
    }
    __shared__ float red[32];
#pragma unroll
    for (int m = 16; m; m >>= 1) local += __shfl_xor_sync(0xffffffffu, local, m);
    if ((tid & 31) == 0) red[tid >> 5] = local;
    __syncthreads();
    if (tid < 32) {
        float v = red[tid];
#pragma unroll
        for (int m = 16; m; m >>= 1) v += __shfl_xor_sync(0xffffffffu, v, m);
        if (tid == 0) out[0] = v * (1.0f / NROWS);
    }
}

// =====================================================================
extern "C" void kernel_launch(void* const* d_in, const int* in_sizes, int n_in,
                              void* d_out, int out_size) {
    const float* x       = (const float*)d_in[0];
    const float* dense_w = (const float*)d_in[1];
    const float* dense_b = (const float*)d_in[2];
    const float* ln_g    = (const float*)d_in[3];
    const float* ln_b    = (const float*)d_in[4];
    const float* dec_w   = (const float*)d_in[5];
    const float* dec_b   = (const float*)d_in[6];
    float* out = (float*)d_out;

    k_gemm1<<<dim3(8, 64), 256>>>(x, dense_w, dense_b);
    k_ln<<<NROWS, 256>>>(ln_g, ln_b);
    k_gemm2<<<NROWS / 32, 256>>>(dec_w, dec_b);
    cudaFuncSetAttribute(k_sims, cudaFuncAttributeMaxDynamicSharedMemorySize, 131072);
    k_sims<<<dim3(NROWS / 128, NSPLIT), 256, 131072>>>();
    k_final<<<1, 1024>>>(out);
}